// round 17
// baseline (speedup 1.0000x reference)
#include <cuda_runtime.h>
#include <cuda_bf16.h>
#include <math.h>
#include <stdint.h>

// PixelContrastLoss via warp-level bf16 tensor cores (mma.sync m16n8k16).
// tcgen05 unavailable (harness builds .target sm_103, no 'a' suffix).
// x [64,128,128] f32, y [64] i32 -> scalar f32.
// N=8192 rows, D=128. loss_i = -log(P/(S+1e-8)+1e-8), mean over rows;
// S_i = sum_j exp(sim_ij - 1) (row max == 1 exactly), P_i masked sum,
// mask(i,j) = (y[i>>7] == y[j&63]) (period-64 in j).
//
// R11: epilogue f32x2 packing (fma.rn.f32x2 / add.rn.f32x2, sm_100+ baseline),
// exp shift folded into one packed FFMA + ex2.approx, mask as packed FMA
// multiplier, merged single final kernel (atomic last-block), knorm MLP=2.

#define NTOT    8192
#define DIM     128
#define TM      128
#define TN      128
#define JSPLIT  16
#define TILES_PER 4          // (NTOT/JSPLIT)/TN
#define THREADS 512
#define NSLOT   16           // JSPLIT slots after in-CTA warp_n reduction

__device__ __align__(16) __nv_bfloat16 g_feat[NTOT * DIM];
__device__ float g_partS[NSLOT * NTOT];
__device__ float g_partP[NSLOT * NTOT];
__device__ float g_red[64];
__device__ int   g_ctr;     // zero-init; last block resets to 0 each run

// smem: A tile 32KB + B double buffer 2x32KB (reused as reduce buffer at end)
#define SA   0
#define SB0  32768
#define SB1  65536
#define SMEM_TOTAL 98304

__device__ __forceinline__ uint32_t smem_u32(const void* p) {
    uint32_t a;
    asm("{ .reg .u64 t; cvta.to.shared.u64 t, %1; cvt.u32.u64 %0, t; }"
        : "=r"(a) : "l"(p));
    return a;
}
__device__ __forceinline__ void ldsm_x4(uint32_t r[4], uint32_t addr) {
    asm volatile("ldmatrix.sync.aligned.m8n8.x4.shared.b16 {%0,%1,%2,%3}, [%4];"
                 : "=r"(r[0]), "=r"(r[1]), "=r"(r[2]), "=r"(r[3]) : "r"(addr));
}
__device__ __forceinline__ void mma16816(float d[4], const uint32_t a[4],
                                         const uint32_t* b) {
    asm volatile(
        "mma.sync.aligned.m16n8k16.row.col.f32.bf16.bf16.f32 "
        "{%0,%1,%2,%3}, {%4,%5,%6,%7}, {%8,%9}, {%0,%1,%2,%3};"
        : "+f"(d[0]), "+f"(d[1]), "+f"(d[2]), "+f"(d[3])
        : "r"(a[0]), "r"(a[1]), "r"(a[2]), "r"(a[3]), "r"(b[0]), "r"(b[1]));
}
#define CP_COMMIT() asm volatile("cp.async.commit_group;" ::: "memory")
#define CP_WAIT0()  asm volatile("cp.async.wait_group 0;" ::: "memory")

// ---- packed f32x2 helpers (sm_100+ baseline PTX, not arch-'a' gated) ------
__device__ __forceinline__ uint64_t pk2(float lo, float hi) {
    uint64_t r;
    asm("mov.b64 %0, {%1, %2};" : "=l"(r) : "f"(lo), "f"(hi));
    return r;
}
__device__ __forceinline__ void upk2(uint64_t v, float& lo, float& hi) {
    asm("mov.b64 {%0, %1}, %2;" : "=f"(lo), "=f"(hi) : "l"(v));
}
__device__ __forceinline__ uint64_t fma2(uint64_t a, uint64_t b, uint64_t c) {
    uint64_t r;
    asm("fma.rn.f32x2 %0, %1, %2, %3;" : "=l"(r) : "l"(a), "l"(b), "l"(c));
    return r;
}
__device__ __forceinline__ uint64_t add2(uint64_t a, uint64_t b) {
    uint64_t r;
    asm("add.rn.f32x2 %0, %1, %2;" : "=l"(r) : "l"(a), "l"(b));
    return r;
}
__device__ __forceinline__ float ex2f(float x) {
    float r;
    asm("ex2.approx.f32 %0, %1;" : "=f"(r) : "f"(x));
    return r;
}
#define L2E 1.4426950408889634f

// Load a 128x128 bf16 tile into swizzled smem via cp.async.
// Row = 256B = 16 chunks of 16B; swizzle: chunk' = chunk ^ (row & 7).
__device__ __forceinline__ void cpa_tile(uint32_t dst, int row0, int tid) {
    #pragma unroll
    for (int it = 0; it < 4; ++it) {
        int i = it * THREADS + tid;
        int r = i >> 4, c = i & 15;
        const void* src =
            (const char*)g_feat + ((size_t)(row0 + r) * DIM + c * 8) * 2;
        uint32_t d = dst + r * 256 + ((c ^ (r & 7)) << 4);
        asm volatile("cp.async.cg.shared.global [%0], [%1], 16;"
                     :: "r"(d), "l"(src));
    }
}

// ---------------------------------------------------------------------------
// 1) L2-normalize + bf16 convert: one warp per 2 rows (MLP=2 per thread).
// ---------------------------------------------------------------------------
__global__ void knorm(const float* __restrict__ x) {
    int w    = blockIdx.x * 8 + (threadIdx.x >> 5);   // 0..4095
    int lane = threadIdx.x & 31;
    int r0 = w, r1 = w + NTOT / 2;
    float4 v0 = ((const float4*)(x + (size_t)r0 * DIM))[lane];
    float4 v1 = ((const float4*)(x + (size_t)r1 * DIM))[lane];
    float s0 = v0.x * v0.x + v0.y * v0.y + v0.z * v0.z + v0.w * v0.w;
    float s1 = v1.x * v1.x + v1.y * v1.y + v1.z * v1.z + v1.w * v1.w;
    #pragma unroll
    for (int o = 16; o; o >>= 1) {
        s0 += __shfl_xor_sync(0xffffffffu, s0, o);
        s1 += __shfl_xor_sync(0xffffffffu, s1, o);
    }
    float i0 = 1.0f / fmaxf(sqrtf(s0), 1e-12f);
    float i1 = 1.0f / fmaxf(sqrtf(s1), 1e-12f);
    __nv_bfloat162 a0 = __floats2bfloat162_rn(v0.x * i0, v0.y * i0);
    __nv_bfloat162 a1 = __floats2bfloat162_rn(v0.z * i0, v0.w * i0);
    __nv_bfloat162 b0 = __floats2bfloat162_rn(v1.x * i1, v1.y * i1);
    __nv_bfloat162 b1 = __floats2bfloat162_rn(v1.z * i1, v1.w * i1);
    uint2 oa, ob;
    oa.x = *(uint32_t*)&a0; oa.y = *(uint32_t*)&a1;
    ob.x = *(uint32_t*)&b0; ob.y = *(uint32_t*)&b1;
    ((uint2*)(g_feat + (size_t)r0 * DIM))[lane] = oa;
    ((uint2*)(g_feat + (size_t)r1 * DIM))[lane] = ob;
}

// ---------------------------------------------------------------------------
// 2) main: 128x128 CTA tile, 16 warps (4x4), warp tile 32x32, K=128.
//    cp.async double-buffered B; packed-f32x2 epilogue from registers.
// ---------------------------------------------------------------------------
__global__ __launch_bounds__(THREADS, 1) void kmain(const int* __restrict__ y) {
    extern __shared__ char smem[];
    const uint32_t sb = smem_u32(smem);
    const int tid = threadIdx.x;
    const int wid = tid >> 5, l = tid & 31;
    const int warp_m = wid >> 2, warp_n = wid & 3;
    const int bx = blockIdx.x, by = blockIdx.y;
    const int i0 = bx * TM;
    const int col0 = by * (NTOT / JSPLIT);

    // packed mask multipliers: mpk[nf*2+par] = {m,m}, m = (y[col%64]==y[bx])
    const int rlab = y[bx];
    uint64_t mpk[8];
    #pragma unroll
    for (int nf = 0; nf < 4; ++nf)
        #pragma unroll
        for (int par = 0; par < 2; ++par) {
            int c = (warp_n & 1) * 32 + nf * 8 + 2 * (l & 3) + par;
            float m = (y[c] == rlab) ? 1.0f : 0.0f;
            mpk[nf * 2 + par] = pk2(m, m);
        }
    const uint64_t kL2E = pk2(L2E, L2E);
    const uint64_t kNL2E = pk2(-L2E, -L2E);

    // prologue: A + B tile 0
    cpa_tile(sb + SA, i0, tid);
    cpa_tile(sb + SB0, col0, tid);
    CP_COMMIT();
    CP_WAIT0();
    __syncthreads();

    // ldmatrix lane geometry
    const int mat = l >> 3, lrow = l & 7;
    uint32_t a_rb[2]; int a_rx[2];
    #pragma unroll
    for (int mf = 0; mf < 2; ++mf) {
        int r = warp_m * 32 + mf * 16 + ((mat & 1) << 3) + lrow;
        a_rb[mf] = sb + SA + r * 256;
        a_rx[mf] = r & 7;
    }
    const int a_kh = mat >> 1;
    uint32_t b_off[2]; int b_rx[2];
    #pragma unroll
    for (int p = 0; p < 2; ++p) {
        int n = warp_n * 32 + p * 16 + ((mat >> 1) << 3) + lrow;
        b_off[p] = n * 256;
        b_rx[p] = n & 7;
    }
    const int b_kh = mat & 1;

    float acc[2][4][4];
    #pragma unroll
    for (int mf = 0; mf < 2; ++mf)
        #pragma unroll
        for (int nf = 0; nf < 4; ++nf)
            #pragma unroll
            for (int d = 0; d < 4; ++d) acc[mf][nf][d] = 0.f;
    uint64_t Sp[2] = {0ull, 0ull}, Pp[2] = {0ull, 0ull};  // {row g, row g+8}

    for (int jt = 0; jt < TILES_PER; ++jt) {
        const uint32_t sbB = sb + ((jt & 1) ? SB1 : SB0);
        if (jt + 1 < TILES_PER) {
            cpa_tile(sb + ((jt & 1) ? SB0 : SB1), col0 + (jt + 1) * TN, tid);
            CP_COMMIT();
        }

        #pragma unroll
        for (int k = 0; k < 8; ++k) {
            uint32_t af[2][4], bf[2][4];
            #pragma unroll
            for (int p = 0; p < 2; ++p)
                ldsm_x4(bf[p], sbB + b_off[p] +
                                   ((((k << 1) + b_kh) ^ b_rx[p]) << 4));
            #pragma unroll
            for (int mf = 0; mf < 2; ++mf)
                ldsm_x4(af[mf],
                        a_rb[mf] + ((((k << 1) + a_kh) ^ a_rx[mf]) << 4));
            #pragma unroll
            for (int mf = 0; mf < 2; ++mf)
                #pragma unroll
                for (int nf = 0; nf < 4; ++nf)
                    mma16816(acc[mf][nf], af[mf], &bf[nf >> 1][(nf & 1) * 2]);
        }

        // packed epilogue: pairs (d0,d2) / (d1,d3) share column => mask bit.
        // exp(v-1) = ex2(v*log2e - log2e): shift folded into the FFMA.
        #pragma unroll
        for (int mf = 0; mf < 2; ++mf)
            #pragma unroll
            for (int nf = 0; nf < 4; ++nf) {
                uint64_t p0 = pk2(acc[mf][nf][0], acc[mf][nf][2]);
                uint64_t p1 = pk2(acc[mf][nf][1], acc[mf][nf][3]);
                uint64_t t0 = fma2(p0, kL2E, kNL2E);
                uint64_t t1 = fma2(p1, kL2E, kNL2E);
                float xa, xb;
                upk2(t0, xa, xb);
                uint64_t e0 = pk2(ex2f(xa), ex2f(xb));
                upk2(t1, xa, xb);
                uint64_t e1 = pk2(ex2f(xa), ex2f(xb));
                Sp[mf] = add2(Sp[mf], e0);
                Sp[mf] = add2(Sp[mf], e1);
                Pp[mf] = fma2(e0, mpk[nf * 2 + 0], Pp[mf]);
                Pp[mf] = fma2(e1, mpk[nf * 2 + 1], Pp[mf]);
                acc[mf][nf][0] = 0.f; acc[mf][nf][1] = 0.f;
                acc[mf][nf][2] = 0.f; acc[mf][nf][3] = 0.f;
            }

        if (jt + 1 < TILES_PER) CP_WAIT0();
        __syncthreads();
    }

    // unpack to per-row scalars: idx = mf*2 + (0:row g, 1:row g+8)
    float rowS[4], rowP[4];
    #pragma unroll
    for (int mf = 0; mf < 2; ++mf) {
        upk2(Sp[mf], rowS[mf * 2 + 0], rowS[mf * 2 + 1]);
        upk2(Pp[mf], rowP[mf * 2 + 0], rowP[mf * 2 + 1]);
    }

    // quad reduce (lanes of a quad share the same rows)
    #pragma unroll
    for (int idx = 0; idx < 4; ++idx) {
        rowS[idx] += __shfl_xor_sync(0xffffffffu, rowS[idx], 1);
        rowS[idx] += __shfl_xor_sync(0xffffffffu, rowS[idx], 2);
        rowP[idx] += __shfl_xor_sync(0xffffffffu, rowP[idx], 1);
        rowP[idx] += __shfl_xor_sync(0xffffffffu, rowP[idx], 2);
    }

    // cross-warp_n reduction via smem (reuse tile buffers; MMAs are done)
    float* red = (float*)smem;      // [4 warp_n][128 rows][2]
    __syncthreads();
    if ((l & 3) == 0) {
        #pragma unroll
        for (int idx = 0; idx < 4; ++idx) {
            int row_local = warp_m * 32 + (idx >> 1) * 16 + (l >> 2) +
                            (idx & 1) * 8;
            red[(warp_n * 128 + row_local) * 2 + 0] = rowS[idx];
            red[(warp_n * 128 + row_local) * 2 + 1] = rowP[idx];
        }
    }
    __syncthreads();
    if (tid < 128) {
        float S = 0.f, P = 0.f;
        #pragma unroll
        for (int wn = 0; wn < 4; ++wn) {
            S += red[(wn * 128 + tid) * 2 + 0];
            P += red[(wn * 128 + tid) * 2 + 1];
        }
        g_partS[by * NTOT + i0 + tid] = S;
        g_partP[by * NTOT + i0 + tid] = P;
    }
}

// ---------------------------------------------------------------------------
// 3) final: 64 blocks; last block folds g_red and writes the mean.
//    g_ctr self-resets -> deterministic across graph replays.
// ---------------------------------------------------------------------------
__global__ void kfinal(float* __restrict__ out) {
    __shared__ float red[4];
    __shared__ bool last;
    int tid = threadIdx.x;
    int row = blockIdx.x * 128 + tid;
    float S = 0.f, P = 0.f;
    #pragma unroll
    for (int s = 0; s < NSLOT; ++s) {
        S += g_partS[s * NTOT + row];
        P += g_partP[s * NTOT + row];
    }
    float acc = -logf(P / (S + 1e-8f) + 1e-8f);
    #pragma unroll
    for (int o = 16; o; o >>= 1) acc += __shfl_xor_sync(0xffffffffu, acc, o);
    if ((tid & 31) == 0) red[tid >> 5] = acc;
    __syncthreads();
    if (tid == 0) {
        g_red[blockIdx.x] = red[0] + red[1] + red[2] + red[3];
        __threadfence();
        int old = atomicAdd(&g_ctr, 1);
        last = (old == 63);
    }
    __syncthreads();
    if (last) {
        if (tid == 0) g_ctr = 0;                    // reset for next replay
        float v = (tid < 64) ? g_red[tid] : 0.f;
        #pragma unroll
        for (int o = 16; o; o >>= 1) v += __shfl_xor_sync(0xffffffffu, v, o);
        __shared__ float r2[4];
        if ((tid & 31) == 0) r2[tid >> 5] = v;
        __syncthreads();
        if (tid == 0) out[0] = (r2[0] + r2[1] + r2[2] + r2[3]) / (float)NTOT;
    }
}

// ---------------------------------------------------------------------------
extern "C" void kernel_launch(void* const* d_in, const int* in_sizes, int n_in,
                              void* d_out, int out_size) {
    const float* x = (const float*)d_in[0];
    const int*   y = (const int*)d_in[1];
    float*     out = (float*)d_out;

    knorm<<<NTOT / 16, 256>>>(x);

    cudaFuncSetAttribute(kmain, cudaFuncAttributeMaxDynamicSharedMemorySize,
                         SMEM_TOTAL);
    kmain<<<dim3(NTOT / TM, JSPLIT), THREADS, SMEM_TOTAL>>>(y);

    kfinal<<<64, 128>>>(out);
}